// round 6
// baseline (speedup 1.0000x reference)
#include <cuda_runtime.h>

#define B_SZ 4
#define C_DIM 256
#define L_DIM 4096
#define N_GROUPS 32
#define C_PG 8          // C_DIM / N_GROUPS

#define CL (C_DIM * L_DIM)          // 1,048,576  per-batch stride for [C,L] tensors
#define LL (L_DIM * L_DIM)          // 16,777,216 per-batch stride for scores

// ---------------- scratch (device globals; no allocation allowed) ----------------
__device__ float g_h [B_SZ * CL];   // normalized input
__device__ float g_q [B_SZ * CL];
__device__ float g_k [B_SZ * CL];
__device__ float g_v [B_SZ * CL];
__device__ float g_h2[B_SZ * CL];   // attention output
__device__ float g_s [B_SZ * LL];   // scores / probs (256 MB)

// ---------------- f32x2 helpers (Blackwell packed fp32, 2x FFMA rate) ----------------
__device__ __forceinline__ unsigned long long pack2(float v) {
    unsigned long long r;
    unsigned int u = __float_as_uint(v);
    asm("mov.b64 %0, {%1, %2};" : "=l"(r) : "r"(u), "r"(u));
    return r;
}
__device__ __forceinline__ void ffma2(unsigned long long& d,
                                      unsigned long long a,
                                      unsigned long long b) {
    asm("fma.rn.f32x2 %0, %1, %2, %0;" : "+l"(d) : "l"(a), "l"(b));
}

// ---------------- GroupNorm ----------------
__global__ void gn_kernel(const float* __restrict__ x,
                          const float* __restrict__ gamma,
                          const float* __restrict__ beta) {
    int b = blockIdx.x / N_GROUPS;
    int g = blockIdx.x % N_GROUPS;
    const int N = C_PG * L_DIM;                       // 32768
    size_t base = ((size_t)b * C_DIM + g * C_PG) * L_DIM;
    const float* xp = x + base;
    float* hp = g_h + base;
    int t = threadIdx.x;

    float s = 0.f, ss = 0.f;
    for (int i = t; i < N; i += 256) {
        float v = xp[i];
        s += v;
        ss = fmaf(v, v, ss);
    }
    #pragma unroll
    for (int o = 16; o; o >>= 1) {
        s  += __shfl_xor_sync(0xffffffffu, s,  o);
        ss += __shfl_xor_sync(0xffffffffu, ss, o);
    }
    __shared__ float shs[8], shss[8];
    if ((t & 31) == 0) { shs[t >> 5] = s; shss[t >> 5] = ss; }
    __syncthreads();
    float ts = 0.f, tss = 0.f;
    #pragma unroll
    for (int w = 0; w < 8; w++) { ts += shs[w]; tss += shss[w]; }

    float mean = ts / (float)N;
    float var  = tss / (float)N - mean * mean;
    float rstd = rsqrtf(var + 1e-6f);

    for (int i = t; i < N; i += 256) {
        int c = g * C_PG + (i >> 12);                 // i / L_DIM
        hp[i] = (xp[i] - mean) * rstd * gamma[c] + beta[c];
    }
}

// ---------------- generic SGEMM:  C[m,n] = alpha * sum_k Ahat[k,m]*Bhat[k,n] (+bias[m]) (+res) ----
// TRA=0: A is [K x M] row-major (Ahat[k,m] = A[k*lda+m])
// TRA=1: A is [M x K] row-major (Ahat[k,m] = A[m*lda+k])    (same for B with n)
#define BM 128
#define BN 128
#define BK 16
#define SROW 132

template<int TRA, int TRB, bool BIAS, bool RES>
__global__ __launch_bounds__(256, 2)
void gemm_kernel(const float* __restrict__ Ab, const float* __restrict__ Bb,
                 const float* __restrict__ bias, const float* __restrict__ Rb,
                 float* __restrict__ Cb,
                 int K, int lda, int ldb, int ldc, float alpha,
                 long sA, long sB, long sR, long sC) {
    const float* A = Ab + (long)blockIdx.z * sA;
    const float* B = Bb + (long)blockIdx.z * sB;
    float* C       = Cb + (long)blockIdx.z * sC;

    int m0 = blockIdx.y * BM;
    int n0 = blockIdx.x * BN;

    __shared__ __align__(16) float As[BK][SROW];
    __shared__ __align__(16) float Bs[BK][SROW];

    int t = threadIdx.x;
    int warp = t >> 5, lane = t & 31;
    int wm = warp >> 1, wn = warp & 1;
    int lm = lane >> 3, ln = lane & 7;
    int mb = wm * 32 + lm * 4;    // rows mb..mb+3 and mb+16..mb+19
    int nb = wn * 64 + ln * 4;    // cols nb..nb+3 and nb+32..nb+35

    unsigned long long acc[8][4];
    #pragma unroll
    for (int i = 0; i < 8; i++)
        #pragma unroll
        for (int j = 0; j < 4; j++) acc[i][j] = 0ull;

    for (int k0 = 0; k0 < K; k0 += BK) {
        // ---- load A tile into As[k][m]
        if (TRA == 0) {
            int ak = t >> 5;
            int am = (t & 31) * 4;
            #pragma unroll
            for (int r = 0; r < 2; r++) {
                int kk = ak + r * 8;
                float4 v = *reinterpret_cast<const float4*>(A + (long)(k0 + kk) * lda + m0 + am);
                *reinterpret_cast<float4*>(&As[kk][am]) = v;
            }
        } else {
            int am  = t >> 1;
            int kq0 = (t & 1) * 2;
            #pragma unroll
            for (int r = 0; r < 2; r++) {
                int kq = kq0 + r;
                float4 v = *reinterpret_cast<const float4*>(A + (long)(m0 + am) * lda + k0 + kq * 4);
                As[kq * 4 + 0][am] = v.x;
                As[kq * 4 + 1][am] = v.y;
                As[kq * 4 + 2][am] = v.z;
                As[kq * 4 + 3][am] = v.w;
            }
        }
        // ---- load B tile into Bs[k][n]
        if (TRB == 0) {
            int bk = t >> 5;
            int bn = (t & 31) * 4;
            #pragma unroll
            for (int r = 0; r < 2; r++) {
                int kk = bk + r * 8;
                float4 v = *reinterpret_cast<const float4*>(B + (long)(k0 + kk) * ldb + n0 + bn);
                *reinterpret_cast<float4*>(&Bs[kk][bn]) = v;
            }
        } else {
            int bn  = t >> 1;
            int kq0 = (t & 1) * 2;
            #pragma unroll
            for (int r = 0; r < 2; r++) {
                int kq = kq0 + r;
                float4 v = *reinterpret_cast<const float4*>(B + (long)(n0 + bn) * ldb + k0 + kq * 4);
                Bs[kq * 4 + 0][bn] = v.x;
                Bs[kq * 4 + 1][bn] = v.y;
                Bs[kq * 4 + 2][bn] = v.z;
                Bs[kq * 4 + 3][bn] = v.w;
            }
        }
        __syncthreads();

        #pragma unroll
        for (int k = 0; k < BK; k++) {
            float4 a0 = *reinterpret_cast<const float4*>(&As[k][mb]);
            float4 a1 = *reinterpret_cast<const float4*>(&As[k][mb + 16]);
            ulonglong2 b0 = *reinterpret_cast<const ulonglong2*>(&Bs[k][nb]);
            ulonglong2 b1 = *reinterpret_cast<const ulonglong2*>(&Bs[k][nb + 32]);
            float a_[8] = {a0.x, a0.y, a0.z, a0.w, a1.x, a1.y, a1.z, a1.w};
            #pragma unroll
            for (int r = 0; r < 8; r++) {
                unsigned long long ap = pack2(a_[r]);
                ffma2(acc[r][0], ap, b0.x);
                ffma2(acc[r][1], ap, b0.y);
                ffma2(acc[r][2], ap, b1.x);
                ffma2(acc[r][3], ap, b1.y);
            }
        }
        __syncthreads();
    }

    // ---- epilogue
    #pragma unroll
    for (int r = 0; r < 8; r++) {
        int m = m0 + mb + ((r < 4) ? r : (r + 12));   // second half at +16
        float bv = BIAS ? bias[m] : 0.0f;
        #pragma unroll
        for (int j = 0; j < 4; j++) {
            int n = n0 + nb + ((j & 1) * 2) + ((j >> 1) * 32);
            float lo = __uint_as_float((unsigned int)(acc[r][j] & 0xffffffffull));
            float hi = __uint_as_float((unsigned int)(acc[r][j] >> 32));
            float2 out;
            out.x = fmaf(alpha, lo, bv);
            out.y = fmaf(alpha, hi, bv);
            if (RES) {
                const float* R = Rb + (long)blockIdx.z * sR;
                float2 rr = *reinterpret_cast<const float2*>(R + (long)m * ldc + n);
                out.x += rr.x;
                out.y += rr.y;
            }
            *reinterpret_cast<float2*>(C + (long)m * ldc + n) = out;
        }
    }
}

// ---------------- row softmax over last dim (4096) ----------------
__global__ void softmax_kernel(float* __restrict__ S) {
    float* p = S + (size_t)blockIdx.x * L_DIM;
    int t = threadIdx.x;
    float4 v[4];
    #pragma unroll
    for (int i = 0; i < 4; i++)
        v[i] = *reinterpret_cast<const float4*>(p + 4 * (i * 256 + t));

    float mx = -3.4e38f;
    #pragma unroll
    for (int i = 0; i < 4; i++)
        mx = fmaxf(mx, fmaxf(fmaxf(v[i].x, v[i].y), fmaxf(v[i].z, v[i].w)));
    #pragma unroll
    for (int o = 16; o; o >>= 1) mx = fmaxf(mx, __shfl_xor_sync(0xffffffffu, mx, o));

    __shared__ float red[8];
    if ((t & 31) == 0) red[t >> 5] = mx;
    __syncthreads();
    #pragma unroll
    for (int w = 0; w < 8; w++) mx = fmaxf(mx, red[w]);
    __syncthreads();

    float sum = 0.f;
    #pragma unroll
    for (int i = 0; i < 4; i++) {
        v[i].x = __expf(v[i].x - mx);
        v[i].y = __expf(v[i].y - mx);
        v[i].z = __expf(v[i].z - mx);
        v[i].w = __expf(v[i].w - mx);
        sum += v[i].x + v[i].y + v[i].z + v[i].w;
    }
    #pragma unroll
    for (int o = 16; o; o >>= 1) sum += __shfl_xor_sync(0xffffffffu, sum, o);
    if ((t & 31) == 0) red[t >> 5] = sum;
    __syncthreads();
    float tot = 0.f;
    #pragma unroll
    for (int w = 0; w < 8; w++) tot += red[w];
    float rinv = 1.0f / tot;

    #pragma unroll
    for (int i = 0; i < 4; i++) {
        v[i].x *= rinv; v[i].y *= rinv; v[i].z *= rinv; v[i].w *= rinv;
        *reinterpret_cast<float4*>(p + 4 * (i * 256 + t)) = v[i];
    }
}

// ---------------- launch ----------------
extern "C" void kernel_launch(void* const* d_in, const int* in_sizes, int n_in,
                              void* d_out, int out_size) {
    const float* x      = (const float*)d_in[0];
    const float* norm_g = (const float*)d_in[1];
    const float* norm_b = (const float*)d_in[2];
    const float* q_w    = (const float*)d_in[3];
    const float* q_b    = (const float*)d_in[4];
    const float* k_w    = (const float*)d_in[5];
    const float* k_b    = (const float*)d_in[6];
    const float* v_w    = (const float*)d_in[7];
    const float* v_b    = (const float*)d_in[8];
    const float* p_w    = (const float*)d_in[9];
    const float* p_b    = (const float*)d_in[10];
    float* out = (float*)d_out;

    float *h, *q, *k, *v, *h2, *s;
    cudaGetSymbolAddress((void**)&h,  g_h);
    cudaGetSymbolAddress((void**)&q,  g_q);
    cudaGetSymbolAddress((void**)&k,  g_k);
    cudaGetSymbolAddress((void**)&v,  g_v);
    cudaGetSymbolAddress((void**)&h2, g_h2);
    cudaGetSymbolAddress((void**)&s,  g_s);

    // 1) group norm
    gn_kernel<<<B_SZ * N_GROUPS, 256>>>(x, norm_g, norm_b);

    // 2) q, k, v = conv1x1(h)       Y[o,l] = sum_c W[o,c] * h[c,l] + b[o]
    dim3 gconv(L_DIM / BN, C_DIM / BM, B_SZ);      // (32, 2, 4)
    gemm_kernel<1, 0, true, false><<<gconv, 256>>>(q_w, h, q_b, nullptr, q,
        C_DIM, C_DIM, L_DIM, L_DIM, 1.0f, 0, CL, 0, CL);
    gemm_kernel<1, 0, true, false><<<gconv, 256>>>(k_w, h, k_b, nullptr, k,
        C_DIM, C_DIM, L_DIM, L_DIM, 1.0f, 0, CL, 0, CL);
    gemm_kernel<1, 0, true, false><<<gconv, 256>>>(v_w, h, v_b, nullptr, v,
        C_DIM, C_DIM, L_DIM, L_DIM, 1.0f, 0, CL, 0, CL);

    // 3) scores S[i,j] = (1/16) * sum_c q[c,i] * k[c,j]
    dim3 gsc(L_DIM / BN, L_DIM / BM, B_SZ);        // (32, 32, 4)
    gemm_kernel<0, 0, false, false><<<gsc, 256>>>(q, k, nullptr, nullptr, s,
        C_DIM, L_DIM, L_DIM, L_DIM, 0.0625f, CL, CL, 0, (long)LL);

    // 4) softmax rows
    softmax_kernel<<<B_SZ * L_DIM, 256>>>(s);

    // 5) h2[c,i] = sum_j v[c,j] * P[i,j]
    gemm_kernel<1, 1, false, false><<<gconv, 256>>>(v, s, nullptr, nullptr, h2,
        L_DIM, L_DIM, L_DIM, L_DIM, 1.0f, CL, (long)LL, 0, CL);

    // 6) out = x + proj(h2)
    gemm_kernel<1, 0, true, true><<<gconv, 256>>>(p_w, h2, p_b, x, out,
        C_DIM, C_DIM, L_DIM, L_DIM, 1.0f, 0, CL, CL, CL);
}